// round 16
// baseline (speedup 1.0000x reference)
#include <cuda_runtime.h>
#include <cuda_bf16.h>
#include <math.h>
#include <stdint.h>

// ---------------------------------------------------------------------------
// Neural ODE block via exact replica of jax.experimental.ode.odeint (DoPri5,
// rtol=atol=1e-3). GEMMs on tensor cores via mma.sync, bf16x3 fp32 emulation,
// phase-merged K-loop ([hi|lo] storage), templated stage_split.
// The gsync between GEMM1 and GEMM2 is replaced by per-tile rowblock
// gating (producer: syncthreads + tid0 fence+atomicAdd; consumer: one
// acquire-load spin per GEMM2 tile). GEMM1's tail overlaps GEMM2's start;
// one fewer grid barrier per f-eval. Elementwise passes stay gsync-ordered
// (round-13 lesson: rowblock-gated elementwise convoys).
// 256-thr CTAs, 128x128 tiles, 2 CTAs/SM.
// ---------------------------------------------------------------------------

#define BN   4096
#define DDIM 1024
#define HDIM 4096
#define NTOT (BN * DDIM)
#define N4   (NTOT / 4)
#define MAXB 1024
#define THREADS 256
#define ATOLF 1e-3f
#define RTOLF 1e-3f

// smem stage: [A_hi | A_lo | B] tiles, each 128 rows x 64 bf16, pitch 144B
#define SPITCH_B 144
#define ATILE_B  (128 * SPITCH_B)          // 18432
#define STAGE_B  (3 * ATILE_B)             // 55296
#define DSMEM_B  (128 + 2 * STAGE_B)       // 110720

// ------------------------- scratch (device globals) ------------------------
__device__ float g_y[NTOT];
__device__ float g_f[NTOT];
__device__ float g_k2[NTOT];
__device__ float g_k3[NTOT];
__device__ float g_k4[NTOT];
__device__ float g_k5[NTOT];
__device__ float g_k6[NTOT];
__device__ float g_k7[NTOT];
__device__ float g_ynew[NTOT];
__device__ float g_yprev[NTOT];
__device__ float g_f0s[NTOT];
__device__ float g_ymidA[NTOT];
__device__ float g_ymidB[NTOT];
__device__ __nv_bfloat16 g_Ya[(size_t)BN * 2 * DDIM];    // state  [hi|lo]
__device__ __nv_bfloat16 g_Ta[(size_t)BN * 2 * HDIM];    // hidden [hi|lo]
__device__ __nv_bfloat16 g_W1t[(size_t)HDIM * 2 * DDIM]; // W1^T   [hi|lo]
__device__ __nv_bfloat16 g_W2t[(size_t)DDIM * 2 * HDIM]; // W2^T   [hi|lo]
__device__ double g_part[MAXB][2];
__device__ volatile unsigned g_gen;
__device__ unsigned g_cnt;
__device__ unsigned g_rb1[32];   // GEMM1 rowblock completion counters

// ------------------------- DoPri5 coefficients -----------------------------
__device__ const double BETA[6][6] = {
    {1.0/5.0, 0, 0, 0, 0, 0},
    {3.0/40.0, 9.0/40.0, 0, 0, 0, 0},
    {44.0/45.0, -56.0/15.0, 32.0/9.0, 0, 0, 0},
    {19372.0/6561.0, -25360.0/2187.0, 64448.0/6561.0, -212.0/729.0, 0, 0},
    {9017.0/3168.0, -355.0/33.0, 46732.0/5247.0, 49.0/176.0, -5103.0/18656.0, 0},
    {35.0/384.0, 0.0, 500.0/1113.0, 125.0/192.0, -2187.0/6784.0, 11.0/84.0}
};

#define E0f ((float)(35.0/384.0 - 1951.0/21600.0))
#define E2f ((float)(500.0/1113.0 - 22642.0/50085.0))
#define E3f ((float)(125.0/192.0 - 451.0/720.0))
#define E4f ((float)(-2187.0/6784.0 - (-12231.0/42400.0)))
#define E5f ((float)(11.0/84.0 - 649.0/6300.0))
#define E6f ((float)(-1.0/60.0))

#define M0f ((float)(6025192743.0/30085553152.0/2.0))
#define M2f ((float)(51252292925.0/65400821598.0/2.0))
#define M3f ((float)(-2691868925.0/45128329728.0/2.0))
#define M4f ((float)(187940372067.0/1594534317056.0/2.0))
#define M5f ((float)(-1776094331.0/19743644256.0/2.0))
#define M6f ((float)(11237099.0/235043384.0/2.0))

// ------------------------- PTX helpers -------------------------------------
__device__ __forceinline__ uint32_t smem_u32(const void* p) {
    uint32_t a;
    asm("{ .reg .u64 t; cvta.to.shared.u64 t, %1; cvt.u32.u64 %0, t; }"
        : "=r"(a) : "l"(p));
    return a;
}

__device__ __forceinline__ void cp_async16(uint32_t saddr, const void* gaddr) {
    asm volatile("cp.async.cg.shared.global [%0], [%1], 16;"
                 :: "r"(saddr), "l"(gaddr) : "memory");
}
__device__ __forceinline__ void cp_commit() {
    asm volatile("cp.async.commit_group;" ::: "memory");
}
__device__ __forceinline__ void cp_wait0() {
    asm volatile("cp.async.wait_group 0;" ::: "memory");
}

__device__ __forceinline__ void ldsm_x4(uint32_t& r0, uint32_t& r1,
                                        uint32_t& r2, uint32_t& r3, uint32_t addr) {
    asm volatile("ldmatrix.sync.aligned.m8n8.x4.shared.b16 {%0,%1,%2,%3}, [%4];"
                 : "=r"(r0), "=r"(r1), "=r"(r2), "=r"(r3) : "r"(addr));
}

__device__ __forceinline__ void mma16816(float& c0, float& c1, float& c2, float& c3,
                                         uint32_t a0, uint32_t a1, uint32_t a2, uint32_t a3,
                                         uint32_t b0, uint32_t b1) {
    asm volatile(
        "mma.sync.aligned.m16n8k16.row.col.f32.bf16.bf16.f32 "
        "{%0,%1,%2,%3}, {%4,%5,%6,%7}, {%8,%9}, {%0,%1,%2,%3};"
        : "+f"(c0), "+f"(c1), "+f"(c2), "+f"(c3)
        : "r"(a0), "r"(a1), "r"(a2), "r"(a3), "r"(b0), "r"(b1));
}

__device__ __forceinline__ unsigned pack_bf2(__nv_bfloat16 a, __nv_bfloat16 b) {
    return (unsigned)__bfloat16_as_ushort(a) | ((unsigned)__bfloat16_as_ushort(b) << 16);
}

__device__ __forceinline__ unsigned ld_acq(const unsigned* p) {
    unsigned v;
    asm volatile("ld.acquire.gpu.global.u32 %0, [%1];"
                 : "=r"(v) : "l"(p) : "memory");
    return v;
}

// spin until *p >= tgt. Consumer reads gated data only via cp.async.cg
// (L2-direct), so no L1-staleness fence is needed.
__device__ __forceinline__ void spin_ge(const unsigned* p, unsigned tgt) {
    while (ld_acq(p) < tgt) __nanosleep(64);
}

// ------------------------- grid barrier ------------------------------------
__device__ __forceinline__ void gsync()
{
    __threadfence();
    __syncthreads();
    if (threadIdx.x == 0) {
        unsigned gen = g_gen;
        if (atomicAdd(&g_cnt, 1u) == gridDim.x - 1u) {
            g_cnt = 0;
            __threadfence();
            g_gen = gen + 1u;
        } else {
            while (g_gen == gen) { __nanosleep(64); }
        }
    }
    __syncthreads();
    __threadfence();
}

// ------------------------- weight transpose + split ------------------------
__device__ __noinline__ void transpose_split(__nv_bfloat16* __restrict__ dst,
                                             const float* __restrict__ W, int K, int N)
{
    extern __shared__ char dsm_ts[];
    float* ts = (float*)dsm_ts;                 // [32][33]
    const int K2 = 2 * K;
    const int tkn = (K >> 5) * (N >> 5);
    const int tnn = N >> 5;
    const int tid = threadIdx.x;
    for (int t = blockIdx.x; t < tkn; t += gridDim.x) {
        const int kt = (t / tnn) << 5;
        const int nt = (t % tnn) << 5;
        __syncthreads();
        for (int idx = tid; idx < 1024; idx += THREADS) {
            int row = idx >> 5, col = idx & 31;
            ts[row * 33 + col] = W[(size_t)(kt + row) * N + nt + col];
        }
        __syncthreads();
        for (int idx = tid; idx < 1024; idx += THREADS) {
            int i = idx >> 5, j = idx & 31;
            int n = nt + i, k = kt + j;
            float v = ts[j * 33 + i];
            __nv_bfloat16 h = __float2bfloat16(v);
            __nv_bfloat16 l = __float2bfloat16(v - __bfloat162float(h));
            __nv_bfloat16* row = dst + (size_t)n * K2;
            row[k] = h; row[K + k] = l;
        }
    }
}

// ------------------------- templated stage combine + split -----------------
template <int CNT>
__device__ __noinline__ void stage_split_t(const float* __restrict__ ybase,
                                           const float* const* ks, const float* dc,
                                           float* __restrict__ fp32_out)
{
    const float* kp[CNT ? CNT : 1];
    float cc[CNT ? CNT : 1];
#pragma unroll
    for (int j = 0; j < CNT; j++) { kp[j] = ks[j]; cc[j] = dc[j]; }

    size_t i0 = (size_t)blockIdx.x * blockDim.x + threadIdx.x;
    size_t st = (size_t)gridDim.x * blockDim.x;
#pragma unroll 2
    for (size_t i = i0; i < N4; i += st) {
        float4 a = ((const float4*)ybase)[i];
        float4 kv[CNT ? CNT : 1];
#pragma unroll
        for (int j = 0; j < CNT; j++) kv[j] = ((const float4*)kp[j])[i];
#pragma unroll
        for (int j = 0; j < CNT; j++) {
            a.x = fmaf(cc[j], kv[j].x, a.x);
            a.y = fmaf(cc[j], kv[j].y, a.y);
            a.z = fmaf(cc[j], kv[j].z, a.z);
            a.w = fmaf(cc[j], kv[j].w, a.w);
        }
        if (fp32_out) ((float4*)fp32_out)[i] = a;
        size_t e = i << 2;
        size_t m = e >> 10;
        int k = (int)(e & 1023);
        __nv_bfloat16 h0 = __float2bfloat16(a.x), h1 = __float2bfloat16(a.y);
        __nv_bfloat16 h2 = __float2bfloat16(a.z), h3 = __float2bfloat16(a.w);
        __nv_bfloat16 l0 = __float2bfloat16(a.x - __bfloat162float(h0));
        __nv_bfloat16 l1 = __float2bfloat16(a.y - __bfloat162float(h1));
        __nv_bfloat16 l2 = __float2bfloat16(a.z - __bfloat162float(h2));
        __nv_bfloat16 l3 = __float2bfloat16(a.w - __bfloat162float(h3));
        uint2 hp, lp;
        hp.x = pack_bf2(h0, h1); hp.y = pack_bf2(h2, h3);
        lp.x = pack_bf2(l0, l1); lp.y = pack_bf2(l2, l3);
        __nv_bfloat16* row = g_Ya + m * (2 * DDIM) + k;
        *(uint2*)row = hp;
        *(uint2*)(row + DDIM) = lp;
    }
}

__device__ void stage_split(const float* ybase, const float* const* ks,
                            const float* dc, int cnt, float* fp32_out)
{
    switch (cnt) {
        case 0: stage_split_t<0>(ybase, ks, dc, fp32_out); break;
        case 1: stage_split_t<1>(ybase, ks, dc, fp32_out); break;
        case 2: stage_split_t<2>(ybase, ks, dc, fp32_out); break;
        case 3: stage_split_t<3>(ybase, ks, dc, fp32_out); break;
        case 4: stage_split_t<4>(ybase, ks, dc, fp32_out); break;
        default: stage_split_t<5>(ybase, ks, dc, fp32_out); break;
    }
}

// ------------------------- phase-merged mma.sync GEMM ----------------------
// C[M,N] = A[M,*] @ B[N,*]^T, bf16x3. A/B stored [hi|lo], row stride 2K.
// mode 0: outF = acc + bias;  mode 1: tanh -> outS [hi|lo] stride 2*Kout
// bump : per-M-rowblock completion counters (tid0 release per tile)
// waitc: per-tile gate — spin waitc[rowblock] >= wtgt before loading
__device__ __noinline__ void gemm_mma(uint32_t smb,
    const __nv_bfloat16* __restrict__ A, const __nv_bfloat16* __restrict__ Bw,
    const float* __restrict__ bias,
    float* __restrict__ outF, __nv_bfloat16* __restrict__ outS,
    int M, int N, int K, int Kout, int mode,
    unsigned* bump, const unsigned* waitc, unsigned wtgt)
{
    const int tid = threadIdx.x;
    const int wid = tid >> 5;
    const int lane = tid & 31;
    const int warp_m = wid & 1;        // 2 warps in M (64 rows)
    const int warp_n = wid >> 1;       // 4 warps in N (32 cols)
    const int tilesN = N >> 7;
    const int ntiles = (M >> 7) * tilesN;
    const int CK = K >> 6;
    const int NIT = 2 * CK;
    const size_t strideBy = (size_t)K * 4;   // bytes per row (2K bf16)
    const size_t loOff = (size_t)K * 2;      // byte offset of lo segment

    const int a_row = (lane & 7) + ((lane >> 3) & 1) * 8;
    const int a_kof = ((lane >> 4) & 1) * 8;
    const int b_row = (lane & 7) + ((lane >> 4) & 1) * 8;
    const int b_kof = ((lane >> 3) & 1) * 8;

    for (int tile = blockIdx.x; tile < ntiles; tile += gridDim.x) {
        const int tmb = tile / tilesN;   // M-rowblock index
        const int tm = tmb << 7;
        const int tn = (tile % tilesN) << 7;
        if (waitc) spin_ge(&waitc[tmb], wtgt);
        const char* gA0 = (const char*)(A  + (size_t)tm * 2 * K);
        const char* gB0 = (const char*)(Bw + (size_t)tn * 2 * K);

        float acc[4][4][4];
#pragma unroll
        for (int i = 0; i < 4; i++)
#pragma unroll
            for (int j = 0; j < 4; j++)
#pragma unroll
                for (int r = 0; r < 4; r++) acc[i][j][r] = 0.f;

#define ISSUE_LOADS(itc, slot) do {                                           \
        uint32_t sbase = smb + (slot) * STAGE_B;                              \
        if ((itc) < CK) {                                                     \
            const char* aHi = gA0 + (size_t)(itc) * 128;                      \
            const char* bHi = gB0 + (size_t)(itc) * 128;                      \
            _Pragma("unroll")                                                 \
            for (int it2 = 0; it2 < 12; it2++) {                              \
                int u = tid + (it2 << 8);                                     \
                int rg = u >> 10;                                             \
                int v = u & 1023;                                             \
                int row = v >> 3, seg = v & 7;                                \
                const char* src = (rg == 0 ? aHi :                            \
                                   (rg == 1 ? aHi + loOff : bHi))             \
                                  + (size_t)row * strideBy + seg * 16;        \
                cp_async16(sbase + rg * ATILE_B + row * SPITCH_B + seg * 16,  \
                           src);                                              \
            }                                                                 \
        } else {                                                              \
            const char* aHi = gA0 + (size_t)((itc) - CK) * 128;               \
            const char* bLo = gB0 + loOff + (size_t)((itc) - CK) * 128;       \
            _Pragma("unroll")                                                 \
            for (int it2 = 0; it2 < 8; it2++) {                               \
                int u = tid + (it2 << 8);                                     \
                int rg = u >> 10;                                             \
                int v = u & 1023;                                             \
                int row = v >> 3, seg = v & 7;                                \
                const char* src = (rg ? bLo : aHi)                            \
                                  + (size_t)row * strideBy + seg * 16;        \
                cp_async16(sbase + (rg ? 2 * ATILE_B : 0)                     \
                           + row * SPITCH_B + seg * 16, src);                 \
            }                                                                 \
        }                                                                     \
        cp_commit();                                                          \
    } while (0)

        ISSUE_LOADS(0, 0);

        for (int itc = 0; itc < NIT; itc++) {
            const int s = itc & 1;
            cp_wait0();
            __syncthreads();          // loads ready + prev slot fully read
            if (itc + 1 < NIT) ISSUE_LOADS(itc + 1, s ^ 1);

            const uint32_t hiBase = smb + s * STAGE_B;
            const uint32_t loBase = hiBase + ATILE_B;
            const uint32_t bBase  = hiBase + 2 * ATILE_B;
            const int dual = (itc < CK);
#pragma unroll
            for (int ks = 0; ks < 4; ks++) {
                uint32_t aa[4][4];
                uint32_t bb[4][2];
#pragma unroll
                for (int mi = 0; mi < 4; mi++) {
                    uint32_t addr = hiBase
                        + (warp_m * 64 + mi * 16 + a_row) * SPITCH_B
                        + (ks * 16 + a_kof) * 2;
                    ldsm_x4(aa[mi][0], aa[mi][1], aa[mi][2], aa[mi][3], addr);
                }
#pragma unroll
                for (int nj = 0; nj < 2; nj++) {
                    uint32_t addr = bBase
                        + (warp_n * 32 + nj * 16 + b_row) * SPITCH_B
                        + (ks * 16 + b_kof) * 2;
                    ldsm_x4(bb[2*nj][0], bb[2*nj][1], bb[2*nj+1][0], bb[2*nj+1][1], addr);
                }
#pragma unroll
                for (int mi = 0; mi < 4; mi++)
#pragma unroll
                    for (int ni = 0; ni < 4; ni++)
                        mma16816(acc[mi][ni][0], acc[mi][ni][1],
                                 acc[mi][ni][2], acc[mi][ni][3],
                                 aa[mi][0], aa[mi][1], aa[mi][2], aa[mi][3],
                                 bb[ni][0], bb[ni][1]);
                if (dual) {
#pragma unroll
                    for (int mi = 0; mi < 4; mi++) {
                        uint32_t addr = loBase
                            + (warp_m * 64 + mi * 16 + a_row) * SPITCH_B
                            + (ks * 16 + a_kof) * 2;
                        ldsm_x4(aa[mi][0], aa[mi][1], aa[mi][2], aa[mi][3], addr);
                    }
#pragma unroll
                    for (int mi = 0; mi < 4; mi++)
#pragma unroll
                        for (int ni = 0; ni < 4; ni++)
                            mma16816(acc[mi][ni][0], acc[mi][ni][1],
                                     acc[mi][ni][2], acc[mi][ni][3],
                                     aa[mi][0], aa[mi][1], aa[mi][2], aa[mi][3],
                                     bb[ni][0], bb[ni][1]);
                }
            }
        }
#undef ISSUE_LOADS

        // ---- epilogue (direct from fragments) ----
        const int mrow0 = tm + warp_m * 64 + (lane >> 2);
        const int ncol0 = tn + warp_n * 32 + (lane & 3) * 2;
#pragma unroll
        for (int mi = 0; mi < 4; mi++) {
#pragma unroll
            for (int ni = 0; ni < 4; ni++) {
                int n0 = ncol0 + ni * 8;
                float b0v = bias[n0], b1v = bias[n0 + 1];
                int m0 = mrow0 + mi * 16;
#pragma unroll
                for (int half = 0; half < 2; half++) {
                    int mr = m0 + half * 8;
                    float v0 = acc[mi][ni][2*half + 0] + b0v;
                    float v1 = acc[mi][ni][2*half + 1] + b1v;
                    if (mode == 0) {
                        *(float2*)(outF + (size_t)mr * N + n0) = make_float2(v0, v1);
                    } else {
                        v0 = tanhf(v0); v1 = tanhf(v1);
                        __nv_bfloat16 h0 = __float2bfloat16(v0);
                        __nv_bfloat16 h1 = __float2bfloat16(v1);
                        __nv_bfloat16 l0 = __float2bfloat16(v0 - __bfloat162float(h0));
                        __nv_bfloat16 l1 = __float2bfloat16(v1 - __bfloat162float(h1));
                        __nv_bfloat16* orow = outS + (size_t)mr * (2 * (size_t)Kout);
                        *(unsigned*)(orow + n0) = pack_bf2(h0, h1);
                        *(unsigned*)(orow + Kout + n0) = pack_bf2(l0, l1);
                    }
                }
            }
        }
        __syncthreads();   // all warps done before next tile reuses smem
        // release: all threads' epilogue stores ordered before the bump
        if (bump && tid == 0) { __threadfence(); atomicAdd(&bump[tmb], 1u); }
    }
}

// ------------------------- reductions (deterministic) -----------------------
__device__ __noinline__ void block_store_partials(double v0, double v1)
{
    extern __shared__ char dsm_rd[];
    double* s0 = (double*)dsm_rd;          // [THREADS]
    double* s1 = s0 + THREADS;
    int t = threadIdx.x;
    s0[t] = v0; s1[t] = v1;
    __syncthreads();
    for (int o = THREADS / 2; o; o >>= 1) {
        if (t < o) { s0[t] += s0[t + o]; s1[t] += s1[t + o]; }
        __syncthreads();
    }
    if (t == 0) { g_part[blockIdx.x][0] = s0[0]; g_part[blockIdx.x][1] = s1[0]; }
    __syncthreads();
}

__device__ __forceinline__ double2 read_totals()
{
    double a = 0.0, b = 0.0;
    for (unsigned i = 0; i < gridDim.x; i++) { a += g_part[i][0]; b += g_part[i][1]; }
    return make_double2(a, b);
}

// ------------------------- elementwise passes ------------------------------
__device__ __noinline__ void copy_pass(float* __restrict__ dst, const float* __restrict__ src)
{
    size_t i0 = (size_t)blockIdx.x * blockDim.x + threadIdx.x;
    size_t st = (size_t)gridDim.x * blockDim.x;
    for (size_t i = i0; i < N4; i += st)
        ((float4*)dst)[i] = ((const float4*)src)[i];
}

__device__ __noinline__ void norm01_pass(const float* __restrict__ y, const float* __restrict__ f)
{
    size_t i0 = (size_t)blockIdx.x * blockDim.x + threadIdx.x;
    size_t st = (size_t)gridDim.x * blockDim.x;
    double a0 = 0.0, a1 = 0.0;
    for (size_t i = i0; i < N4; i += st) {
        float4 yv = ((const float4*)y)[i];
        float4 fv = ((const float4*)f)[i];
#define CMP(c) { float sc = ATOLF + RTOLF * fabsf(yv.c); \
                 float r0 = yv.c / sc; float r1 = fv.c / sc; \
                 a0 += (double)r0 * (double)r0; a1 += (double)r1 * (double)r1; }
        CMP(x) CMP(y) CMP(z) CMP(w)
#undef CMP
    }
    block_store_partials(a0, a1);
}

__device__ __noinline__ void diffnorm_pass(const float* __restrict__ f1, const float* __restrict__ f0,
                                           const float* __restrict__ y)
{
    size_t i0 = (size_t)blockIdx.x * blockDim.x + threadIdx.x;
    size_t st = (size_t)gridDim.x * blockDim.x;
    double a0 = 0.0;
    for (size_t i = i0; i < N4; i += st) {
        float4 av = ((const float4*)f1)[i];
        float4 bv = ((const float4*)f0)[i];
        float4 yv = ((const float4*)y)[i];
#define CMP(c) { float sc = ATOLF + RTOLF * fabsf(yv.c); \
                 float r = (av.c - bv.c) / sc; a0 += (double)r * (double)r; }
        CMP(x) CMP(y) CMP(z) CMP(w)
#undef CMP
    }
    block_store_partials(a0, 0.0);
}

__device__ __noinline__ void err_mid_pass(const float* __restrict__ y, const float* __restrict__ yn,
                                          const float* __restrict__ k1, const float* __restrict__ k3,
                                          const float* __restrict__ k4, const float* __restrict__ k5,
                                          const float* __restrict__ k6, const float* __restrict__ k7v,
                                          float dt, float* __restrict__ ymid)
{
    size_t i0 = (size_t)blockIdx.x * blockDim.x + threadIdx.x;
    size_t st = (size_t)gridDim.x * blockDim.x;
    double acc = 0.0;
    for (size_t i = i0; i < N4; i += st) {
        float4 yv  = ((const float4*)y)[i];
        float4 ynv = ((const float4*)yn)[i];
        float4 k1v = ((const float4*)k1)[i];
        float4 k3v = ((const float4*)k3)[i];
        float4 k4v = ((const float4*)k4)[i];
        float4 k5v = ((const float4*)k5)[i];
        float4 k6v = ((const float4*)k6)[i];
        float4 k7vv = ((const float4*)k7v)[i];
        float4 mv;
#define CMP(c) { \
        float se = fmaf(E0f, k1v.c, fmaf(E2f, k3v.c, fmaf(E3f, k4v.c, \
                   fmaf(E4f, k5v.c, fmaf(E5f, k6v.c, E6f * k7vv.c))))); \
        float err = dt * se; \
        float sm = fmaf(M0f, k1v.c, fmaf(M2f, k3v.c, fmaf(M3f, k4v.c, \
                   fmaf(M4f, k5v.c, fmaf(M5f, k6v.c, M6f * k7vv.c))))); \
        mv.c = fmaf(dt, sm, yv.c); \
        float tol = ATOLF + RTOLF * fmaxf(fabsf(yv.c), fabsf(ynv.c)); \
        float r = err / tol; acc += (double)r * (double)r; }
        CMP(x) CMP(y) CMP(z) CMP(w)
#undef CMP
        ((float4*)ymid)[i] = mv;
    }
    block_store_partials(acc, 0.0);
}

__device__ __noinline__ void final_pass(float* __restrict__ out,
                                        const float* __restrict__ y0a, const float* __restrict__ y1a,
                                        const float* __restrict__ f0a, const float* __restrict__ f1a,
                                        const float* __restrict__ yma, float h, float rel)
{
    size_t i0 = (size_t)blockIdx.x * blockDim.x + threadIdx.x;
    size_t st = (size_t)gridDim.x * blockDim.x;
    for (size_t i = i0; i < N4; i += st) {
        float4 y0v = ((const float4*)y0a)[i];
        float4 y1v = ((const float4*)y1a)[i];
        float4 f0v = ((const float4*)f0a)[i];
        float4 f1v = ((const float4*)f1a)[i];
        float4 ymv = ((const float4*)yma)[i];
        float4 ov;
#define CMP(c) { \
        float hf0 = h * f0v.c, hf1 = h * f1v.c; \
        float A = -2.f*hf0 + 2.f*hf1 - 8.f*y0v.c - 8.f*y1v.c + 16.f*ymv.c; \
        float Bc = 5.f*hf0 - 3.f*hf1 + 18.f*y0v.c + 14.f*y1v.c - 32.f*ymv.c; \
        float Cc = -4.f*hf0 + hf1 - 11.f*y0v.c - 5.f*y1v.c + 16.f*ymv.c; \
        float Dc = hf0; \
        float Ec = y0v.c; \
        ov.c = fmaf(fmaf(fmaf(fmaf(A, rel, Bc), rel, Cc), rel, Dc), rel, Ec); }
        CMP(x) CMP(y) CMP(z) CMP(w)
#undef CMP
        ((float4*)out)[i] = ov;
    }
}

// ------------------------- f = tanh(.@W1+b1)@W2+b2 on pre-split g_Ya -------
// GEMM1 bumps g_rb1 per rowblock; GEMM2 gates per tile. No middle gsync.
__device__ void feval(uint32_t smb, float* fout, const float* b1, const float* b2,
                      unsigned& e1)
{
    gsync();   // g_Ya fully written by all blocks
    e1++;
    gemm_mma(smb, g_Ya, g_W1t, b1, nullptr, g_Ta, BN, HDIM, DDIM, HDIM, 1,
             g_rb1, nullptr, 0u);
    gemm_mma(smb, g_Ta, g_W2t, b2, fout, nullptr, BN, DDIM, HDIM, 0, 0,
             nullptr, g_rb1, e1 * 32u);
    gsync();
}

// ------------------------- persistent solver kernel ------------------------
__global__ void __launch_bounds__(THREADS, 2)
node_kernel(const float* __restrict__ x,
            const float* __restrict__ W1, const float* __restrict__ b1,
            const float* __restrict__ W2, const float* __restrict__ b2,
            float* __restrict__ out)
{
    extern __shared__ char dsm[];
    uint32_t smb = (smem_u32(dsm) + 127u) & ~127u;

    // reset rowblock counters (ordered before first use by feval's gsync)
    if (blockIdx.x == 0 && threadIdx.x < 32) g_rb1[threadIdx.x] = 0;

    transpose_split(g_W1t, W1, DDIM, HDIM);
    transpose_split(g_W2t, W2, HDIM, DDIM);

    float* y       = g_y;
    float* f       = g_f;
    float* ynew    = g_ynew;
    float* yprev   = g_yprev;
    float* f0s     = g_f0s;
    float* k7      = g_k7;
    float* ymid_sv = g_ymidA;
    float* ymid_c  = g_ymidB;

    unsigned e1 = 0;

    // y = x fused into the initial split
    stage_split(x, nullptr, nullptr, 0, g_y);
    feval(smb, f, b1, b2, e1);                      // f0

    // ---- initial step size (Hairer heuristic, order=4) ----
    norm01_pass(y, f);
    gsync();
    double2 nn = read_totals();
    float d0 = (float)sqrt(nn.x);
    float d1 = (float)sqrt(nn.y);
    float h0 = (d0 < 1e-5f || d1 < 1e-5f) ? 1e-6f : 0.01f * d0 / d1;

    {
        const float* ks1[1] = { f };
        float dc1[1] = { h0 };
        stage_split(y, ks1, dc1, 1, nullptr);       // split(y + h0*f)
        feval(smb, g_k2, b1, b2, e1);               // f1 (scratch in k2)
        diffnorm_pass(g_k2, f, y);
        gsync();
        double2 dd = read_totals();
        float d2 = (float)sqrt(dd.x) / h0;
        float h1;
        if (d1 <= 1e-15f && d2 <= 1e-15f)
            h1 = fmaxf(1e-6f, h0 * 1e-3f);
        else
            h1 = powf(0.01f / fmaxf(d1, d2), 0.2f);
        float dt0 = fminf(100.f * h0, h1);
        if (dt0 < 0.f) dt0 = 0.f;

        float t = 0.f, last_t = 0.f, h_used = 0.f, dt = dt0;
        int any_accept = 0;
        int steps = 0;

        while (t < 1.0f && steps < 1000 && dt > 0.f) {
            const float* kss[7] = { f, g_k2, g_k3, g_k4, g_k5, g_k6, k7 };
            float* kw[7]        = { f, g_k2, g_k3, g_k4, g_k5, g_k6, k7 };

            for (int s = 1; s < 7; s++) {
                const float* kl[6]; float dc[6]; int cnt = 0;
                for (int j = 0; j < s; j++) {
                    double bb = BETA[s - 1][j];
                    if (bb != 0.0) { kl[cnt] = kss[j]; dc[cnt] = dt * (float)bb; cnt++; }
                }
                // stage input y + sum; fp32 copy only needed for s==6 (== ynew)
                stage_split(y, kl, dc, cnt, (s == 6) ? ynew : nullptr);
                feval(smb, kw[s], b1, b2, e1);
            }

            err_mid_pass(y, ynew, f, g_k3, g_k4, g_k5, g_k6, k7, dt, ymid_c);
            gsync();
            double2 ee = read_totals();
            float err_ratio = (float)sqrt(ee.x / (double)NTOT);
            float next_t = t + dt;

            float dtn;
            if (err_ratio == 0.f) {
                dtn = dt * 10.f;
            } else {
                float dfac = (err_ratio < 1.f) ? 1.f : 0.2f;
                float factor = fminf(10.f, fmaxf(0.9f * powf(err_ratio, -0.2f), dfac));
                dtn = dt * factor;
            }
            if (dtn < 0.f) dtn = 0.f;

            if (err_ratio <= 1.f) {
                last_t = t; t = next_t; h_used = dt; any_accept = 1;
                float* tmp = yprev; yprev = y; y = ynew; ynew = tmp;
                tmp = f0s; f0s = f; f = k7; k7 = tmp;
                tmp = ymid_sv; ymid_sv = ymid_c; ymid_c = tmp;
            }
            dt = dtn;
            steps++;
        }

        gsync();
        if (any_accept && t > last_t) {
            float rel = (1.0f - last_t) / (t - last_t);
            final_pass(out, yprev, y, f0s, f, ymid_sv, h_used, rel);
        } else {
            copy_pass(out, y);
        }
        gsync();
    }
}

// ------------------------- launcher ----------------------------------------
extern "C" void kernel_launch(void* const* d_in, const int* in_sizes, int n_in,
                              void* d_out, int out_size)
{
    (void)in_sizes; (void)n_in; (void)out_size;
    const float* x  = (const float*)d_in[0];
    const float* W1 = (const float*)d_in[1];
    const float* b1 = (const float*)d_in[2];
    const float* W2 = (const float*)d_in[3];
    const float* b2 = (const float*)d_in[4];
    float* out = (float*)d_out;

    int dev = 0;
    cudaGetDevice(&dev);
    int sms = 148;
    cudaDeviceGetAttribute(&sms, cudaDevAttrMultiProcessorCount, dev);

    const size_t dsmem = DSMEM_B;   // 110720 per CTA
    cudaFuncSetAttribute(node_kernel, cudaFuncAttributeMaxDynamicSharedMemorySize,
                         (int)dsmem);

    int occ = 1;
    cudaOccupancyMaxActiveBlocksPerMultiprocessor(&occ, node_kernel, THREADS, dsmem);
    if (occ < 1) occ = 1;
    if (occ > 2) occ = 2;          // 2 CTAs/SM
    int nb = sms * occ;
    if (nb > MAXB) nb = MAXB;

    node_kernel<<<nb, THREADS, dsmem>>>(x, W1, b1, W2, b2, out);
}

// round 17
// speedup vs baseline: 1.0043x; 1.0043x over previous
#include <cuda_runtime.h>
#include <cuda_bf16.h>
#include <math.h>
#include <stdint.h>

// ---------------------------------------------------------------------------
// Neural ODE block via exact replica of jax.experimental.ode.odeint (DoPri5,
// rtol=atol=1e-3). GEMMs on tensor cores via mma.sync, bf16x3 fp32 emulation,
// phase-merged K-loop ([hi|lo] storage), templated stage_split.
// Round-14 champion + (1) tid0-only release fence in gsync, (2) epilogue
// barrier removed (next-tile stage overwrites are ordered by the chunk-loop
// syncs; NIT is even for both GEMMs). 256-thr CTAs, 128x128 tiles, 2 CTAs/SM.
// ---------------------------------------------------------------------------

#define BN   4096
#define DDIM 1024
#define HDIM 4096
#define NTOT (BN * DDIM)
#define N4   (NTOT / 4)
#define MAXB 1024
#define THREADS 256
#define ATOLF 1e-3f
#define RTOLF 1e-3f

// smem stage: [A_hi | A_lo | B] tiles, each 128 rows x 64 bf16, pitch 144B
#define SPITCH_B 144
#define ATILE_B  (128 * SPITCH_B)          // 18432
#define STAGE_B  (3 * ATILE_B)             // 55296
#define DSMEM_B  (128 + 2 * STAGE_B)       // 110720

// ------------------------- scratch (device globals) ------------------------
__device__ float g_y[NTOT];
__device__ float g_f[NTOT];
__device__ float g_k2[NTOT];
__device__ float g_k3[NTOT];
__device__ float g_k4[NTOT];
__device__ float g_k5[NTOT];
__device__ float g_k6[NTOT];
__device__ float g_k7[NTOT];
__device__ float g_ynew[NTOT];
__device__ float g_yprev[NTOT];
__device__ float g_f0s[NTOT];
__device__ float g_ymidA[NTOT];
__device__ float g_ymidB[NTOT];
__device__ __nv_bfloat16 g_Ya[(size_t)BN * 2 * DDIM];    // state  [hi|lo]
__device__ __nv_bfloat16 g_Ta[(size_t)BN * 2 * HDIM];    // hidden [hi|lo]
__device__ __nv_bfloat16 g_W1t[(size_t)HDIM * 2 * DDIM]; // W1^T   [hi|lo]
__device__ __nv_bfloat16 g_W2t[(size_t)DDIM * 2 * HDIM]; // W2^T   [hi|lo]
__device__ double g_part[MAXB][2];
__device__ volatile unsigned g_gen;
__device__ unsigned g_cnt;

// ------------------------- DoPri5 coefficients -----------------------------
__device__ const double BETA[6][6] = {
    {1.0/5.0, 0, 0, 0, 0, 0},
    {3.0/40.0, 9.0/40.0, 0, 0, 0, 0},
    {44.0/45.0, -56.0/15.0, 32.0/9.0, 0, 0, 0},
    {19372.0/6561.0, -25360.0/2187.0, 64448.0/6561.0, -212.0/729.0, 0, 0},
    {9017.0/3168.0, -355.0/33.0, 46732.0/5247.0, 49.0/176.0, -5103.0/18656.0, 0},
    {35.0/384.0, 0.0, 500.0/1113.0, 125.0/192.0, -2187.0/6784.0, 11.0/84.0}
};

#define E0f ((float)(35.0/384.0 - 1951.0/21600.0))
#define E2f ((float)(500.0/1113.0 - 22642.0/50085.0))
#define E3f ((float)(125.0/192.0 - 451.0/720.0))
#define E4f ((float)(-2187.0/6784.0 - (-12231.0/42400.0)))
#define E5f ((float)(11.0/84.0 - 649.0/6300.0))
#define E6f ((float)(-1.0/60.0))

#define M0f ((float)(6025192743.0/30085553152.0/2.0))
#define M2f ((float)(51252292925.0/65400821598.0/2.0))
#define M3f ((float)(-2691868925.0/45128329728.0/2.0))
#define M4f ((float)(187940372067.0/1594534317056.0/2.0))
#define M5f ((float)(-1776094331.0/19743644256.0/2.0))
#define M6f ((float)(11237099.0/235043384.0/2.0))

// ------------------------- PTX helpers -------------------------------------
__device__ __forceinline__ uint32_t smem_u32(const void* p) {
    uint32_t a;
    asm("{ .reg .u64 t; cvta.to.shared.u64 t, %1; cvt.u32.u64 %0, t; }"
        : "=r"(a) : "l"(p));
    return a;
}

__device__ __forceinline__ void cp_async16(uint32_t saddr, const void* gaddr) {
    asm volatile("cp.async.cg.shared.global [%0], [%1], 16;"
                 :: "r"(saddr), "l"(gaddr) : "memory");
}
__device__ __forceinline__ void cp_commit() {
    asm volatile("cp.async.commit_group;" ::: "memory");
}
__device__ __forceinline__ void cp_wait0() {
    asm volatile("cp.async.wait_group 0;" ::: "memory");
}

__device__ __forceinline__ void ldsm_x4(uint32_t& r0, uint32_t& r1,
                                        uint32_t& r2, uint32_t& r3, uint32_t addr) {
    asm volatile("ldmatrix.sync.aligned.m8n8.x4.shared.b16 {%0,%1,%2,%3}, [%4];"
                 : "=r"(r0), "=r"(r1), "=r"(r2), "=r"(r3) : "r"(addr));
}

__device__ __forceinline__ void mma16816(float& c0, float& c1, float& c2, float& c3,
                                         uint32_t a0, uint32_t a1, uint32_t a2, uint32_t a3,
                                         uint32_t b0, uint32_t b1) {
    asm volatile(
        "mma.sync.aligned.m16n8k16.row.col.f32.bf16.bf16.f32 "
        "{%0,%1,%2,%3}, {%4,%5,%6,%7}, {%8,%9}, {%0,%1,%2,%3};"
        : "+f"(c0), "+f"(c1), "+f"(c2), "+f"(c3)
        : "r"(a0), "r"(a1), "r"(a2), "r"(a3), "r"(b0), "r"(b1));
}

__device__ __forceinline__ unsigned pack_bf2(__nv_bfloat16 a, __nv_bfloat16 b) {
    return (unsigned)__bfloat16_as_ushort(a) | ((unsigned)__bfloat16_as_ushort(b) << 16);
}

// ------------------------- grid barrier ------------------------------------
// Release: syncthreads orders intra-CTA stores before tid0's fence
// (cumulativity), so only tid0 pays the MEMBAR. Acquire: trailing fence in
// all threads invalidates L1 for post-barrier reads of peer data.
__device__ __forceinline__ void gsync()
{
    __syncthreads();
    if (threadIdx.x == 0) {
        __threadfence();
        unsigned gen = g_gen;
        if (atomicAdd(&g_cnt, 1u) == gridDim.x - 1u) {
            g_cnt = 0;
            __threadfence();
            g_gen = gen + 1u;
        } else {
            while (g_gen == gen) { __nanosleep(64); }
        }
    }
    __syncthreads();
    __threadfence();
}

// ------------------------- weight transpose + split ------------------------
__device__ __noinline__ void transpose_split(__nv_bfloat16* __restrict__ dst,
                                             const float* __restrict__ W, int K, int N)
{
    extern __shared__ char dsm_ts[];
    float* ts = (float*)dsm_ts;                 // [32][33]
    const int K2 = 2 * K;
    const int tkn = (K >> 5) * (N >> 5);
    const int tnn = N >> 5;
    const int tid = threadIdx.x;
    for (int t = blockIdx.x; t < tkn; t += gridDim.x) {
        const int kt = (t / tnn) << 5;
        const int nt = (t % tnn) << 5;
        __syncthreads();
        for (int idx = tid; idx < 1024; idx += THREADS) {
            int row = idx >> 5, col = idx & 31;
            ts[row * 33 + col] = W[(size_t)(kt + row) * N + nt + col];
        }
        __syncthreads();
        for (int idx = tid; idx < 1024; idx += THREADS) {
            int i = idx >> 5, j = idx & 31;
            int n = nt + i, k = kt + j;
            float v = ts[j * 33 + i];
            __nv_bfloat16 h = __float2bfloat16(v);
            __nv_bfloat16 l = __float2bfloat16(v - __bfloat162float(h));
            __nv_bfloat16* row = dst + (size_t)n * K2;
            row[k] = h; row[K + k] = l;
        }
    }
}

// ------------------------- templated stage combine + split -----------------
template <int CNT>
__device__ __noinline__ void stage_split_t(const float* __restrict__ ybase,
                                           const float* const* ks, const float* dc,
                                           float* __restrict__ fp32_out)
{
    const float* kp[CNT ? CNT : 1];
    float cc[CNT ? CNT : 1];
#pragma unroll
    for (int j = 0; j < CNT; j++) { kp[j] = ks[j]; cc[j] = dc[j]; }

    size_t i0 = (size_t)blockIdx.x * blockDim.x + threadIdx.x;
    size_t st = (size_t)gridDim.x * blockDim.x;
#pragma unroll 2
    for (size_t i = i0; i < N4; i += st) {
        float4 a = ((const float4*)ybase)[i];
        float4 kv[CNT ? CNT : 1];
#pragma unroll
        for (int j = 0; j < CNT; j++) kv[j] = ((const float4*)kp[j])[i];
#pragma unroll
        for (int j = 0; j < CNT; j++) {
            a.x = fmaf(cc[j], kv[j].x, a.x);
            a.y = fmaf(cc[j], kv[j].y, a.y);
            a.z = fmaf(cc[j], kv[j].z, a.z);
            a.w = fmaf(cc[j], kv[j].w, a.w);
        }
        if (fp32_out) ((float4*)fp32_out)[i] = a;
        size_t e = i << 2;
        size_t m = e >> 10;
        int k = (int)(e & 1023);
        __nv_bfloat16 h0 = __float2bfloat16(a.x), h1 = __float2bfloat16(a.y);
        __nv_bfloat16 h2 = __float2bfloat16(a.z), h3 = __float2bfloat16(a.w);
        __nv_bfloat16 l0 = __float2bfloat16(a.x - __bfloat162float(h0));
        __nv_bfloat16 l1 = __float2bfloat16(a.y - __bfloat162float(h1));
        __nv_bfloat16 l2 = __float2bfloat16(a.z - __bfloat162float(h2));
        __nv_bfloat16 l3 = __float2bfloat16(a.w - __bfloat162float(h3));
        uint2 hp, lp;
        hp.x = pack_bf2(h0, h1); hp.y = pack_bf2(h2, h3);
        lp.x = pack_bf2(l0, l1); lp.y = pack_bf2(l2, l3);
        __nv_bfloat16* row = g_Ya + m * (2 * DDIM) + k;
        *(uint2*)row = hp;
        *(uint2*)(row + DDIM) = lp;
    }
}

__device__ void stage_split(const float* ybase, const float* const* ks,
                            const float* dc, int cnt, float* fp32_out)
{
    switch (cnt) {
        case 0: stage_split_t<0>(ybase, ks, dc, fp32_out); break;
        case 1: stage_split_t<1>(ybase, ks, dc, fp32_out); break;
        case 2: stage_split_t<2>(ybase, ks, dc, fp32_out); break;
        case 3: stage_split_t<3>(ybase, ks, dc, fp32_out); break;
        case 4: stage_split_t<4>(ybase, ks, dc, fp32_out); break;
        default: stage_split_t<5>(ybase, ks, dc, fp32_out); break;
    }
}

// ------------------------- phase-merged mma.sync GEMM ----------------------
// C[M,N] = A[M,*] @ B[N,*]^T, bf16x3. A/B stored [hi|lo], row stride 2K.
// Phase A (CK chunks): load A_hi,A_lo,B_hi -> acc += Ah*Bh + Al*Bh
// Phase B (CK chunks): load A_hi,B_lo     -> acc += Ah*Bl
// mode 0: outF = acc + bias;  mode 1: tanh -> outS [hi|lo] stride 2*Kout
__device__ __noinline__ void gemm_mma(uint32_t smb,
    const __nv_bfloat16* __restrict__ A, const __nv_bfloat16* __restrict__ Bw,
    const float* __restrict__ bias,
    float* __restrict__ outF, __nv_bfloat16* __restrict__ outS,
    int M, int N, int K, int Kout, int mode)
{
    const int tid = threadIdx.x;
    const int wid = tid >> 5;
    const int lane = tid & 31;
    const int warp_m = wid & 1;        // 2 warps in M (64 rows)
    const int warp_n = wid >> 1;       // 4 warps in N (32 cols)
    const int tilesN = N >> 7;
    const int ntiles = (M >> 7) * tilesN;
    const int CK = K >> 6;
    const int NIT = 2 * CK;            // even for both GEMMs
    const size_t strideBy = (size_t)K * 4;   // bytes per row (2K bf16)
    const size_t loOff = (size_t)K * 2;      // byte offset of lo segment

    const int a_row = (lane & 7) + ((lane >> 3) & 1) * 8;
    const int a_kof = ((lane >> 4) & 1) * 8;
    const int b_row = (lane & 7) + ((lane >> 4) & 1) * 8;
    const int b_kof = ((lane >> 3) & 1) * 8;

    for (int tile = blockIdx.x; tile < ntiles; tile += gridDim.x) {
        const int tm = (tile / tilesN) << 7;
        const int tn = (tile % tilesN) << 7;
        const char* gA0 = (const char*)(A  + (size_t)tm * 2 * K);
        const char* gB0 = (const char*)(Bw + (size_t)tn * 2 * K);

        float acc[4][4][4];
#pragma unroll
        for (int i = 0; i < 4; i++)
#pragma unroll
            for (int j = 0; j < 4; j++)
#pragma unroll
                for (int r = 0; r < 4; r++) acc[i][j][r] = 0.f;

#define ISSUE_LOADS(itc, slot) do {                                           \
        uint32_t sbase = smb + (slot) * STAGE_B;                              \
        if ((itc) < CK) {                                                     \
            const char* aHi = gA0 + (size_t)(itc) * 128;                      \
            const char* bHi = gB0 + (size_t)(itc) * 128;                      \
            _Pragma("unroll")                                                 \
            for (int it2 = 0; it2 < 12; it2++) {                              \
                int u = tid + (it2 << 8);                                     \
                int rg = u >> 10;                                             \
                int v = u & 1023;                                             \
                int row = v >> 3, seg = v & 7;                                \
                const char* src = (rg == 0 ? aHi :                            \
                                   (rg == 1 ? aHi + loOff : bHi))             \
                                  + (size_t)row * strideBy + seg * 16;        \
                cp_async16(sbase + rg * ATILE_B + row * SPITCH_B + seg * 16,  \
                           src);                                              \
            }                                                                 \
        } else {                                                              \
            const char* aHi = gA0 + (size_t)((itc) - CK) * 128;               \
            const char* bLo = gB0 + loOff + (size_t)((itc) - CK) * 128;       \
            _Pragma("unroll")                                                 \
            for (int it2 = 0; it2 < 8; it2++) {                               \
                int u = tid + (it2 << 8);                                     \
                int rg = u >> 10;                                             \
                int v = u & 1023;                                             \
                int row = v >> 3, seg = v & 7;                                \
                const char* src = (rg ? bLo : aHi)                            \
                                  + (size_t)row * strideBy + seg * 16;        \
                cp_async16(sbase + (rg ? 2 * ATILE_B : 0)                     \
                           + row * SPITCH_B + seg * 16, src);                 \
            }                                                                 \
        }                                                                     \
        cp_commit();                                                          \
    } while (0)

        ISSUE_LOADS(0, 0);

        for (int itc = 0; itc < NIT; itc++) {
            const int s = itc & 1;
            cp_wait0();
            __syncthreads();          // loads ready + prev slot fully read
            if (itc + 1 < NIT) ISSUE_LOADS(itc + 1, s ^ 1);

            const uint32_t hiBase = smb + s * STAGE_B;
            const uint32_t loBase = hiBase + ATILE_B;
            const uint32_t bBase  = hiBase + 2 * ATILE_B;
            const int dual = (itc < CK);
#pragma unroll
            for (int ks = 0; ks < 4; ks++) {
                uint32_t aa[4][4];
                uint32_t bb[4][2];
#pragma unroll
                for (int mi = 0; mi < 4; mi++) {
                    uint32_t addr = hiBase
                        + (warp_m * 64 + mi * 16 + a_row) * SPITCH_B
                        + (ks * 16 + a_kof) * 2;
                    ldsm_x4(aa[mi][0], aa[mi][1], aa[mi][2], aa[mi][3], addr);
                }
#pragma unroll
                for (int nj = 0; nj < 2; nj++) {
                    uint32_t addr = bBase
                        + (warp_n * 32 + nj * 16 + b_row) * SPITCH_B
                        + (ks * 16 + b_kof) * 2;
                    ldsm_x4(bb[2*nj][0], bb[2*nj][1], bb[2*nj+1][0], bb[2*nj+1][1], addr);
                }
#pragma unroll
                for (int mi = 0; mi < 4; mi++)
#pragma unroll
                    for (int ni = 0; ni < 4; ni++)
                        mma16816(acc[mi][ni][0], acc[mi][ni][1],
                                 acc[mi][ni][2], acc[mi][ni][3],
                                 aa[mi][0], aa[mi][1], aa[mi][2], aa[mi][3],
                                 bb[ni][0], bb[ni][1]);
                if (dual) {
#pragma unroll
                    for (int mi = 0; mi < 4; mi++) {
                        uint32_t addr = loBase
                            + (warp_m * 64 + mi * 16 + a_row) * SPITCH_B
                            + (ks * 16 + a_kof) * 2;
                        ldsm_x4(aa[mi][0], aa[mi][1], aa[mi][2], aa[mi][3], addr);
                    }
#pragma unroll
                    for (int mi = 0; mi < 4; mi++)
#pragma unroll
                        for (int ni = 0; ni < 4; ni++)
                            mma16816(acc[mi][ni][0], acc[mi][ni][1],
                                     acc[mi][ni][2], acc[mi][ni][3],
                                     aa[mi][0], aa[mi][1], aa[mi][2], aa[mi][3],
                                     bb[ni][0], bb[ni][1]);
                }
            }
        }
#undef ISSUE_LOADS

        // ---- epilogue (direct from fragments; no trailing barrier:
        //      next tile's stage overwrites are ordered by chunk-loop syncs) ----
        const int mrow0 = tm + warp_m * 64 + (lane >> 2);
        const int ncol0 = tn + warp_n * 32 + (lane & 3) * 2;
#pragma unroll
        for (int mi = 0; mi < 4; mi++) {
#pragma unroll
            for (int ni = 0; ni < 4; ni++) {
                int n0 = ncol0 + ni * 8;
                float b0v = bias[n0], b1v = bias[n0 + 1];
                int m0 = mrow0 + mi * 16;
#pragma unroll
                for (int half = 0; half < 2; half++) {
                    int mr = m0 + half * 8;
                    float v0 = acc[mi][ni][2*half + 0] + b0v;
                    float v1 = acc[mi][ni][2*half + 1] + b1v;
                    if (mode == 0) {
                        *(float2*)(outF + (size_t)mr * N + n0) = make_float2(v0, v1);
                    } else {
                        v0 = tanhf(v0); v1 = tanhf(v1);
                        __nv_bfloat16 h0 = __float2bfloat16(v0);
                        __nv_bfloat16 h1 = __float2bfloat16(v1);
                        __nv_bfloat16 l0 = __float2bfloat16(v0 - __bfloat162float(h0));
                        __nv_bfloat16 l1 = __float2bfloat16(v1 - __bfloat162float(h1));
                        __nv_bfloat16* orow = outS + (size_t)mr * (2 * (size_t)Kout);
                        *(unsigned*)(orow + n0) = pack_bf2(h0, h1);
                        *(unsigned*)(orow + Kout + n0) = pack_bf2(l0, l1);
                    }
                }
            }
        }
    }
}

// ------------------------- reductions (deterministic) -----------------------
__device__ __noinline__ void block_store_partials(double v0, double v1)
{
    extern __shared__ char dsm_rd[];
    double* s0 = (double*)dsm_rd;          // [THREADS]
    double* s1 = s0 + THREADS;
    int t = threadIdx.x;
    __syncthreads();                       // smem reuse safety
    s0[t] = v0; s1[t] = v1;
    __syncthreads();
    for (int o = THREADS / 2; o; o >>= 1) {
        if (t < o) { s0[t] += s0[t + o]; s1[t] += s1[t + o]; }
        __syncthreads();
    }
    if (t == 0) { g_part[blockIdx.x][0] = s0[0]; g_part[blockIdx.x][1] = s1[0]; }
    __syncthreads();
}

__device__ __forceinline__ double2 read_totals()
{
    double a = 0.0, b = 0.0;
    for (unsigned i = 0; i < gridDim.x; i++) { a += g_part[i][0]; b += g_part[i][1]; }
    return make_double2(a, b);
}

// ------------------------- elementwise passes ------------------------------
__device__ __noinline__ void copy_pass(float* __restrict__ dst, const float* __restrict__ src)
{
    size_t i0 = (size_t)blockIdx.x * blockDim.x + threadIdx.x;
    size_t st = (size_t)gridDim.x * blockDim.x;
    for (size_t i = i0; i < N4; i += st)
        ((float4*)dst)[i] = ((const float4*)src)[i];
}

__device__ __noinline__ void norm01_pass(const float* __restrict__ y, const float* __restrict__ f)
{
    size_t i0 = (size_t)blockIdx.x * blockDim.x + threadIdx.x;
    size_t st = (size_t)gridDim.x * blockDim.x;
    double a0 = 0.0, a1 = 0.0;
    for (size_t i = i0; i < N4; i += st) {
        float4 yv = ((const float4*)y)[i];
        float4 fv = ((const float4*)f)[i];
#define CMP(c) { float sc = ATOLF + RTOLF * fabsf(yv.c); \
                 float r0 = yv.c / sc; float r1 = fv.c / sc; \
                 a0 += (double)r0 * (double)r0; a1 += (double)r1 * (double)r1; }
        CMP(x) CMP(y) CMP(z) CMP(w)
#undef CMP
    }
    block_store_partials(a0, a1);
}

__device__ __noinline__ void diffnorm_pass(const float* __restrict__ f1, const float* __restrict__ f0,
                                           const float* __restrict__ y)
{
    size_t i0 = (size_t)blockIdx.x * blockDim.x + threadIdx.x;
    size_t st = (size_t)gridDim.x * blockDim.x;
    double a0 = 0.0;
    for (size_t i = i0; i < N4; i += st) {
        float4 av = ((const float4*)f1)[i];
        float4 bv = ((const float4*)f0)[i];
        float4 yv = ((const float4*)y)[i];
#define CMP(c) { float sc = ATOLF + RTOLF * fabsf(yv.c); \
                 float r = (av.c - bv.c) / sc; a0 += (double)r * (double)r; }
        CMP(x) CMP(y) CMP(z) CMP(w)
#undef CMP
    }
    block_store_partials(a0, 0.0);
}

__device__ __noinline__ void err_mid_pass(const float* __restrict__ y, const float* __restrict__ yn,
                                          const float* __restrict__ k1, const float* __restrict__ k3,
                                          const float* __restrict__ k4, const float* __restrict__ k5,
                                          const float* __restrict__ k6, const float* __restrict__ k7v,
                                          float dt, float* __restrict__ ymid)
{
    size_t i0 = (size_t)blockIdx.x * blockDim.x + threadIdx.x;
    size_t st = (size_t)gridDim.x * blockDim.x;
    double acc = 0.0;
    for (size_t i = i0; i < N4; i += st) {
        float4 yv  = ((const float4*)y)[i];
        float4 ynv = ((const float4*)yn)[i];
        float4 k1v = ((const float4*)k1)[i];
        float4 k3v = ((const float4*)k3)[i];
        float4 k4v = ((const float4*)k4)[i];
        float4 k5v = ((const float4*)k5)[i];
        float4 k6v = ((const float4*)k6)[i];
        float4 k7vv = ((const float4*)k7v)[i];
        float4 mv;
#define CMP(c) { \
        float se = fmaf(E0f, k1v.c, fmaf(E2f, k3v.c, fmaf(E3f, k4v.c, \
                   fmaf(E4f, k5v.c, fmaf(E5f, k6v.c, E6f * k7vv.c))))); \
        float err = dt * se; \
        float sm = fmaf(M0f, k1v.c, fmaf(M2f, k3v.c, fmaf(M3f, k4v.c, \
                   fmaf(M4f, k5v.c, fmaf(M5f, k6v.c, M6f * k7vv.c))))); \
        mv.c = fmaf(dt, sm, yv.c); \
        float tol = ATOLF + RTOLF * fmaxf(fabsf(yv.c), fabsf(ynv.c)); \
        float r = err / tol; acc += (double)r * (double)r; }
        CMP(x) CMP(y) CMP(z) CMP(w)
#undef CMP
        ((float4*)ymid)[i] = mv;
    }
    block_store_partials(acc, 0.0);
}

__device__ __noinline__ void final_pass(float* __restrict__ out,
                                        const float* __restrict__ y0a, const float* __restrict__ y1a,
                                        const float* __restrict__ f0a, const float* __restrict__ f1a,
                                        const float* __restrict__ yma, float h, float rel)
{
    size_t i0 = (size_t)blockIdx.x * blockDim.x + threadIdx.x;
    size_t st = (size_t)gridDim.x * blockDim.x;
    for (size_t i = i0; i < N4; i += st) {
        float4 y0v = ((const float4*)y0a)[i];
        float4 y1v = ((const float4*)y1a)[i];
        float4 f0v = ((const float4*)f0a)[i];
        float4 f1v = ((const float4*)f1a)[i];
        float4 ymv = ((const float4*)yma)[i];
        float4 ov;
#define CMP(c) { \
        float hf0 = h * f0v.c, hf1 = h * f1v.c; \
        float A = -2.f*hf0 + 2.f*hf1 - 8.f*y0v.c - 8.f*y1v.c + 16.f*ymv.c; \
        float Bc = 5.f*hf0 - 3.f*hf1 + 18.f*y0v.c + 14.f*y1v.c - 32.f*ymv.c; \
        float Cc = -4.f*hf0 + hf1 - 11.f*y0v.c - 5.f*y1v.c + 16.f*ymv.c; \
        float Dc = hf0; \
        float Ec = y0v.c; \
        ov.c = fmaf(fmaf(fmaf(fmaf(A, rel, Bc), rel, Cc), rel, Dc), rel, Ec); }
        CMP(x) CMP(y) CMP(z) CMP(w)
#undef CMP
        ((float4*)out)[i] = ov;
    }
}

// ------------------------- f = tanh(.@W1+b1)@W2+b2 on pre-split g_Ya -------
__device__ void feval(uint32_t smb, float* fout, const float* b1, const float* b2)
{
    gsync();   // g_Ya fully written by all blocks
    gemm_mma(smb, g_Ya, g_W1t, b1, nullptr, g_Ta, BN, HDIM, DDIM, HDIM, 1);
    gsync();
    gemm_mma(smb, g_Ta, g_W2t, b2, fout, nullptr, BN, DDIM, HDIM, 0, 0);
    gsync();
}

// ------------------------- persistent solver kernel ------------------------
__global__ void __launch_bounds__(THREADS, 2)
node_kernel(const float* __restrict__ x,
            const float* __restrict__ W1, const float* __restrict__ b1,
            const float* __restrict__ W2, const float* __restrict__ b2,
            float* __restrict__ out)
{
    extern __shared__ char dsm[];
    uint32_t smb = (smem_u32(dsm) + 127u) & ~127u;

    transpose_split(g_W1t, W1, DDIM, HDIM);
    transpose_split(g_W2t, W2, HDIM, DDIM);

    float* y       = g_y;
    float* f       = g_f;
    float* ynew    = g_ynew;
    float* yprev   = g_yprev;
    float* f0s     = g_f0s;
    float* k7      = g_k7;
    float* ymid_sv = g_ymidA;
    float* ymid_c  = g_ymidB;

    // y = x fused into the initial split
    stage_split(x, nullptr, nullptr, 0, g_y);
    feval(smb, f, b1, b2);                          // f0

    // ---- initial step size (Hairer heuristic, order=4) ----
    norm01_pass(y, f);
    gsync();
    double2 nn = read_totals();
    float d0 = (float)sqrt(nn.x);
    float d1 = (float)sqrt(nn.y);
    float h0 = (d0 < 1e-5f || d1 < 1e-5f) ? 1e-6f : 0.01f * d0 / d1;

    {
        const float* ks1[1] = { f };
        float dc1[1] = { h0 };
        stage_split(y, ks1, dc1, 1, nullptr);       // split(y + h0*f)
        feval(smb, g_k2, b1, b2);                   // f1 (scratch in k2)
        diffnorm_pass(g_k2, f, y);
        gsync();
        double2 dd = read_totals();
        float d2 = (float)sqrt(dd.x) / h0;
        float h1;
        if (d1 <= 1e-15f && d2 <= 1e-15f)
            h1 = fmaxf(1e-6f, h0 * 1e-3f);
        else
            h1 = powf(0.01f / fmaxf(d1, d2), 0.2f);
        float dt0 = fminf(100.f * h0, h1);
        if (dt0 < 0.f) dt0 = 0.f;

        float t = 0.f, last_t = 0.f, h_used = 0.f, dt = dt0;
        int any_accept = 0;
        int steps = 0;

        while (t < 1.0f && steps < 1000 && dt > 0.f) {
            const float* kss[7] = { f, g_k2, g_k3, g_k4, g_k5, g_k6, k7 };
            float* kw[7]        = { f, g_k2, g_k3, g_k4, g_k5, g_k6, k7 };

            for (int s = 1; s < 7; s++) {
                const float* kl[6]; float dc[6]; int cnt = 0;
                for (int j = 0; j < s; j++) {
                    double bb = BETA[s - 1][j];
                    if (bb != 0.0) { kl[cnt] = kss[j]; dc[cnt] = dt * (float)bb; cnt++; }
                }
                // stage input y + sum; fp32 copy only needed for s==6 (== ynew)
                stage_split(y, kl, dc, cnt, (s == 6) ? ynew : nullptr);
                feval(smb, kw[s], b1, b2);
            }

            err_mid_pass(y, ynew, f, g_k3, g_k4, g_k5, g_k6, k7, dt, ymid_c);
            gsync();
            double2 ee = read_totals();
            float err_ratio = (float)sqrt(ee.x / (double)NTOT);
            float next_t = t + dt;

            float dtn;
            if (err_ratio == 0.f) {
                dtn = dt * 10.f;
            } else {
                float dfac = (err_ratio < 1.f) ? 1.f : 0.2f;
                float factor = fminf(10.f, fmaxf(0.9f * powf(err_ratio, -0.2f), dfac));
                dtn = dt * factor;
            }
            if (dtn < 0.f) dtn = 0.f;

            if (err_ratio <= 1.f) {
                last_t = t; t = next_t; h_used = dt; any_accept = 1;
                float* tmp = yprev; yprev = y; y = ynew; ynew = tmp;
                tmp = f0s; f0s = f; f = k7; k7 = tmp;
                tmp = ymid_sv; ymid_sv = ymid_c; ymid_c = tmp;
            }
            dt = dtn;
            steps++;
        }

        gsync();
        if (any_accept && t > last_t) {
            float rel = (1.0f - last_t) / (t - last_t);
            final_pass(out, yprev, y, f0s, f, ymid_sv, h_used, rel);
        } else {
            copy_pass(out, y);
        }
        gsync();
    }
}

// ------------------------- launcher ----------------------------------------
extern "C" void kernel_launch(void* const* d_in, const int* in_sizes, int n_in,
                              void* d_out, int out_size)
{
    (void)in_sizes; (void)n_in; (void)out_size;
    const float* x  = (const float*)d_in[0];
    const float* W1 = (const float*)d_in[1];
    const float* b1 = (const float*)d_in[2];
    const float* W2 = (const float*)d_in[3];
    const float* b2 = (const float*)d_in[4];
    float* out = (float*)d_out;

    int dev = 0;
    cudaGetDevice(&dev);
    int sms = 148;
    cudaDeviceGetAttribute(&sms, cudaDevAttrMultiProcessorCount, dev);

    const size_t dsmem = DSMEM_B;   // 110720 per CTA
    cudaFuncSetAttribute(node_kernel, cudaFuncAttributeMaxDynamicSharedMemorySize,
                         (int)dsmem);

    int occ = 1;
    cudaOccupancyMaxActiveBlocksPerMultiprocessor(&occ, node_kernel, THREADS, dsmem);
    if (occ < 1) occ = 1;
    if (occ > 2) occ = 2;          // 2 CTAs/SM
    int nb = sms * occ;
    if (nb > MAXB) nb = MAXB;

    node_kernel<<<nb, THREADS, dsmem>>>(x, W1, b1, W2, b2, out);
}